// round 11
// baseline (speedup 1.0000x reference)
#include <cuda_runtime.h>
#include <cuda_bf16.h>
#include <cstdint>

#define NUM_E 1024
#define EDIM  256
#define NROWS 32768

// ---- device scratch ----
__device__ float g_cbnorm[NUM_E];                  // ||e_k||^2
__device__ float g_cbT[EDIM * NUM_E];              // codebook transposed [c][k]
__device__ unsigned g_wmaxbits;                    // max ||e||^2 as float bits (nonneg)
__device__ int   g_idx[NROWS];                     // final argmin
__device__ __nv_bfloat16 g_b0[NUM_E * EDIM];       // bf16(codebook) [k][c]
__device__ __nv_bfloat16 g_z0[256 * 8 * 32 * 128]; // bf16(z) tiled [mtile][ch][cr][m]
__device__ __nv_bfloat16 g_dmat[(size_t)NROWS * NUM_E]; // approx distances (64MB)

// ---- smem layout for screen kernel (bytes) ----
#define AS_STRIDE 272                 // 128 m * 2B + 16 pad
#define AS_BUF    (32 * AS_STRIDE)    // 8704
#define BS_OFF    (2 * AS_BUF)        // 17408
#define BS_STRIDE 80
#define BS_BUF    (128 * BS_STRIDE)   // 10240
#define SMEM_TOTAL (BS_OFF + 2 * BS_BUF)  // 37888

__device__ __forceinline__ uint32_t smem_u32(const void* p) {
    uint32_t a;
    asm("{ .reg .u64 t; cvta.to.shared.u64 t, %1; cvt.u32.u64 %0, t; }" : "=r"(a) : "l"(p));
    return a;
}
__device__ __forceinline__ void cpasync16(uint32_t dst, const void* src) {
    asm volatile("cp.async.cg.shared.global [%0], [%1], 16;" :: "r"(dst), "l"(src));
}
__device__ __forceinline__ void ldsm_x4(uint32_t* r, uint32_t addr) {
    asm volatile("ldmatrix.sync.aligned.m8n8.x4.shared.b16 {%0,%1,%2,%3}, [%4];"
                 : "=r"(r[0]), "=r"(r[1]), "=r"(r[2]), "=r"(r[3]) : "r"(addr));
}
__device__ __forceinline__ void ldsm_x4t(uint32_t* r, uint32_t addr) {
    asm volatile("ldmatrix.sync.aligned.m8n8.x4.trans.shared.b16 {%0,%1,%2,%3}, [%4];"
                 : "=r"(r[0]), "=r"(r[1]), "=r"(r[2]), "=r"(r[3]) : "r"(addr));
}
__device__ __forceinline__ void mma16816(float* c, const uint32_t* a, uint32_t b0, uint32_t b1) {
    asm volatile("mma.sync.aligned.m16n8k16.row.col.f32.bf16.bf16.f32 "
                 "{%0,%1,%2,%3}, {%4,%5,%6,%7}, {%8,%9}, {%0,%1,%2,%3};"
                 : "+f"(c[0]), "+f"(c[1]), "+f"(c[2]), "+f"(c[3])
                 : "r"(a[0]), "r"(a[1]), "r"(a[2]), "r"(a[3]), "r"(b0), "r"(b1));
}
__device__ __forceinline__ unsigned ordf(float d) {
    unsigned u = __float_as_uint(d);
    return (u & 0x80000000u) ? ~u : (u | 0x80000000u);
}

// ---------- merged prep: blocks [0,1024) codebook, [1024,3072) z ----------
__global__ __launch_bounds__(256) void prep_kernel(const float* __restrict__ cb,
                                                   const float* __restrict__ z) {
    const int bid = blockIdx.x, t = threadIdx.x;
    if (bid < 1024) {
        int k = bid;
        float v = cb[(size_t)k * EDIM + t];
        g_cbT[(size_t)t * NUM_E + k] = v;
        g_b0[(size_t)k * EDIM + t] = __float2bfloat16(v);
        float sq = v * v;
        #pragma unroll
        for (int o = 16; o; o >>= 1) sq += __shfl_down_sync(0xffffffffu, sq, o);
        __shared__ float ws[8];
        if ((t & 31) == 0) ws[t >> 5] = sq;
        __syncthreads();
        if (t == 0) {
            float s = 0.f;
            #pragma unroll
            for (int i = 0; i < 8; i++) s += ws[i];
            g_cbnorm[k] = s;
            atomicMax(&g_wmaxbits, __float_as_uint(s));
        }
    } else {
        const int zb = bid - 1024;               // zb = mtile*8 + ch
        const int mtile = zb >> 3, ch = zb & 7;
        const int cr = t >> 3, ms = (t & 7) * 16;
        const int m0 = mtile * 128;
        const float* src = z + ((size_t)(m0 >> 10) << 18) + (size_t)(ch * 32 + cr) * 1024 + (m0 & 1023) + ms;
        uint32_t o0[8];
        #pragma unroll
        for (int q = 0; q < 4; q++) {
            float4 f = ((const float4*)src)[q];
            __nv_bfloat162 v0 = __halves2bfloat162(__float2bfloat16(f.x), __float2bfloat16(f.y));
            __nv_bfloat162 v1 = __halves2bfloat162(__float2bfloat16(f.z), __float2bfloat16(f.w));
            o0[q * 2] = *(uint32_t*)&v0; o0[q * 2 + 1] = *(uint32_t*)&v1;
        }
        __nv_bfloat16* dst = g_z0 + ((size_t)zb * 32 + cr) * 128 + ms;
        ((uint4*)dst)[0] = *(uint4*)&o0[0];
        ((uint4*)dst)[1] = *(uint4*)&o0[4];
    }
}

// ---- async tile loaders ----
__device__ __forceinline__ void issue_A(uint32_t dst, int mtile, int ch, int tid) {
    #pragma unroll
    for (int r = 0; r < 2; r++) {
        int e = tid + r * 256;
        int seg = e & 15, cr = e >> 4;
        cpasync16(dst + cr * AS_STRIDE + seg * 16,
                  g_z0 + ((size_t)(mtile * 8 + ch) * 32 + cr) * 128 + seg * 8);
    }
}
__device__ __forceinline__ void issue_B(uint32_t dst, int n0, int c0, int tid) {
    #pragma unroll
    for (int r = 0; r < 2; r++) {
        int e = tid + r * 256;
        int seg = e & 3, bn = e >> 2;
        cpasync16(dst + bn * BS_STRIDE + seg * 16,
                  g_b0 + (size_t)(n0 + bn) * EDIM + c0 + seg * 8);
    }
}

// ---------- screen: bf16 GEMM -> approx distance matrix (bf16) ----------
// grid = 2048 (256 mtiles x 8 ntiles), block = 256
__global__ __launch_bounds__(256, 2) void screen_kernel() {
    extern __shared__ __align__(16) unsigned char smem[];
    const uint32_t sb = smem_u32(smem);
    const int tid = threadIdx.x;
    const int lane = tid & 31;
    const int w = tid >> 5, wm = w & 1, wn = w >> 1;   // 2 m-warps x 4 n-warps
    const int ntile = blockIdx.x & 7, mtile = blockIdx.x >> 3;
    const int m0 = mtile * 128, n0 = ntile * 128;

    float acc[4][4][4];
    #pragma unroll
    for (int i = 0; i < 4; i++)
        #pragma unroll
        for (int j = 0; j < 4; j++)
            #pragma unroll
            for (int e = 0; e < 4; e++) acc[i][j][e] = 0.f;

    issue_A(sb, mtile, 0, tid);
    issue_B(sb + BS_OFF, n0, 0, tid);
    asm volatile("cp.async.commit_group;");

    const int sel = lane >> 3, rr = lane & 7;
    #pragma unroll 1
    for (int ch = 0; ch < 8; ch++) {
        const int buf = ch & 1;
        if (ch < 7) {
            const int nbuf = buf ^ 1;
            issue_A(sb + nbuf * AS_BUF, mtile, ch + 1, tid);
            issue_B(sb + BS_OFF + nbuf * BS_BUF, n0, (ch + 1) * 32, tid);
            asm volatile("cp.async.commit_group;");
            asm volatile("cp.async.wait_group 1;");
        } else {
            asm volatile("cp.async.wait_group 0;");
        }
        __syncthreads();

        const uint32_t asB = sb + buf * AS_BUF;
        const uint32_t bsB = sb + BS_OFF + buf * BS_BUF;
        #pragma unroll
        for (int ks = 0; ks < 2; ks++) {
            const int k0 = ks * 16;
            uint32_t bb[8];
            uint32_t baddr = bsB + (wn * 32 + (sel >> 1) * 8 + rr) * BS_STRIDE + (k0 + (sel & 1) * 8) * 2;
            ldsm_x4(bb, baddr);
            ldsm_x4(bb + 4, baddr + 16 * BS_STRIDE);
            #pragma unroll
            for (int i = 0; i < 4; i++) {
                uint32_t a[4];
                uint32_t aaddr = asB + (k0 + (sel >> 1) * 8 + rr) * AS_STRIDE
                               + (wm * 64 + i * 16 + (sel & 1) * 8) * 2;
                ldsm_x4t(a, aaddr);
                #pragma unroll
                for (int j = 0; j < 4; j++)
                    mma16816(acc[i][j], a, bb[2 * j], bb[2 * j + 1]);
            }
        }
        __syncthreads();
    }

    // epilogue: d~ = ||e||^2 - 2 s0, store bf16
    const int g = lane >> 2, tg = lane & 3;
    float cbn[8];
    #pragma unroll
    for (int j = 0; j < 4; j++) {
        cbn[2 * j]     = __ldg(&g_cbnorm[n0 + wn * 32 + j * 8 + tg * 2]);
        cbn[2 * j + 1] = __ldg(&g_cbnorm[n0 + wn * 32 + j * 8 + tg * 2 + 1]);
    }
    #pragma unroll
    for (int i = 0; i < 4; i++) {
        #pragma unroll
        for (int h = 0; h < 2; h++) {
            int row = m0 + wm * 64 + i * 16 + h * 8 + g;
            #pragma unroll
            for (int j = 0; j < 4; j++) {
                float d0 = cbn[2 * j]     - 2.0f * acc[i][j][h * 2];
                float d1 = cbn[2 * j + 1] - 2.0f * acc[i][j][h * 2 + 1];
                int col = n0 + wn * 32 + j * 8 + tg * 2;
                __nv_bfloat162 v = __halves2bfloat162(__float2bfloat16(d0), __float2bfloat16(d1));
                *(uint32_t*)(g_dmat + (size_t)row * NUM_E + col) = *(uint32_t*)&v;
            }
        }
    }
}

// ---------- pass 2: scan + exact refine (warp per row, 8 rows/block) ----------
// per-lane candidate refinement: no ballots, one final key reduction
__global__ __launch_bounds__(256) void refine_kernel(const float* __restrict__ z,
                                                     const float* __restrict__ cb) {
    __shared__ float zrow[8][256];
    const int bid = blockIdx.x, tid = threadIdx.x;
    const int w = tid >> 5, lane = tid & 31;
    const int r0 = bid * 8, b = r0 >> 10, hw0 = r0 & 1023;
    for (int e = tid; e < 2048; e += 256) {
        int rr = e & 7, c = e >> 3;
        zrow[rr][c] = z[(size_t)b * 262144 + (size_t)c * 1024 + hw0 + rr];
    }
    __syncthreads();
    const int row = r0 + w;

    float zn2 = 0.f;
    #pragma unroll
    for (int i = 0; i < 8; i++) { float v = zrow[w][lane + 32 * i]; zn2 += v * v; }
    #pragma unroll
    for (int o = 16; o; o >>= 1) zn2 += __shfl_xor_sync(0xffffffffu, zn2, o);

    // vectorized dmat scan: 4 x uint4 (8 bf16 each); dv[iq*8+j] -> col (iq*32+lane)*8+j
    const uint4* d4 = (const uint4*)(g_dmat + (size_t)row * NUM_E) + lane;
    uint4 qv[4];
    #pragma unroll
    for (int i = 0; i < 4; i++) qv[i] = d4[i * 32];
    float dv[32];
    float dmin = 3.4e38f;
    #pragma unroll
    for (int i = 0; i < 4; i++) {
        const uint32_t* pp = (const uint32_t*)&qv[i];
        #pragma unroll
        for (int hj = 0; hj < 4; hj++) {
            __nv_bfloat162 h = *(const __nv_bfloat162*)&pp[hj];
            float lo = __bfloat162float(__low2bfloat16(h));
            float hi = __bfloat162float(__high2bfloat16(h));
            dv[i * 8 + hj * 2]     = lo;
            dv[i * 8 + hj * 2 + 1] = hi;
            dmin = fminf(dmin, fminf(lo, hi));
        }
    }
    #pragma unroll
    for (int o = 16; o; o >>= 1) dmin = fminf(dmin, __shfl_xor_sync(0xffffffffu, dmin, o));

    float wmax = sqrtf(__uint_as_float(g_wmaxbits));      // max ||e||
    float T = dmin + 0.025f * sqrtf(zn2) * wmax + 8.0f;   // >3x proven bound

    // per-lane exact refinement of this lane's candidates (no warp sync needed)
    unsigned long long best = ~0ull;
    #pragma unroll 1
    for (int i = 0; i < 32; i++) {
        if (dv[i] <= T) {
            int kc = ((i >> 3) * 32 + lane) * 8 + (i & 7);
            const float4* e4 = (const float4*)(cb + (size_t)kc * EDIM);
            const float* zr = zrow[w];
            float s = 0.f;
            #pragma unroll 8
            for (int c4 = 0; c4 < 64; c4++) {
                float4 e = __ldg(&e4[c4]);
                s += zr[c4 * 4] * e.x + zr[c4 * 4 + 1] * e.y
                   + zr[c4 * 4 + 2] * e.z + zr[c4 * 4 + 3] * e.w;
            }
            float dist = __ldg(&g_cbnorm[kc]) - 2.0f * s;
            unsigned long long key = ((unsigned long long)ordf(dist) << 32) | (unsigned)kc;
            if (key < best) best = key;
        }
    }
    // final warp reduction
    #pragma unroll
    for (int o = 16; o; o >>= 1) {
        unsigned long long ob = __shfl_xor_sync(0xffffffffu, best, o);
        if (ob < best) best = ob;
    }
    if (lane == 0) g_idx[row] = (int)(best & 0xFFFFFFFFu);
}

// ---------- outputs: quant gather (blocks < 8192), one-hot scatter (rest) ----------
__global__ __launch_bounds__(256) void finish_kernel(float* __restrict__ oh, float* __restrict__ oq) {
    int bid = blockIdx.x, t = threadIdx.x;
    if (bid < 8192) {
        int i = bid * 256 + t;
        int flat = i * 4;
        int hw = flat & 1023, c = (flat >> 10) & 255, b = flat >> 18;
        int r0 = b * 1024 + hw;
        int4 idx4;
        idx4.x = g_idx[r0]; idx4.y = g_idx[r0 + 1]; idx4.z = g_idx[r0 + 2]; idx4.w = g_idx[r0 + 3];
        const float* rowp = &g_cbT[(size_t)c * NUM_E];
        float4 v;
        v.x = rowp[idx4.x]; v.y = rowp[idx4.y]; v.z = rowp[idx4.z]; v.w = rowp[idx4.w];
        *(float4*)&oq[flat] = v;
    } else {
        int row = (bid - 8192) * 256 + t;
        oh[(size_t)row * NUM_E + g_idx[row]] = 1.0f;
    }
}

extern "C" void kernel_launch(void* const* d_in, const int* in_sizes, int n_in,
                              void* d_out, int out_size) {
    const float* z  = (const float*)d_in[0];
    const float* cb = (const float*)d_in[1];
    float* out_onehot = (float*)d_out;
    float* out_q      = (float*)d_out + (size_t)NROWS * NUM_E;

    cudaFuncSetAttribute(screen_kernel, cudaFuncAttributeMaxDynamicSharedMemorySize, SMEM_TOTAL);

    cudaMemsetAsync(out_onehot, 0, (size_t)NROWS * NUM_E * sizeof(float));
    prep_kernel<<<3072, 256>>>(cb, z);
    screen_kernel<<<2048, 256, SMEM_TOTAL>>>();
    refine_kernel<<<NROWS / 8, 256>>>(z, cb);
    finish_kernel<<<8192 + NROWS / 256, 256>>>(out_onehot, out_q);
}

// round 12
// speedup vs baseline: 1.9751x; 1.9751x over previous
#include <cuda_runtime.h>
#include <cuda_bf16.h>
#include <cstdint>

#define NUM_E 1024
#define EDIM  256
#define NROWS 32768

// ---- device scratch ----
__device__ float g_cbnorm[NUM_E];                  // ||e_k||^2
__device__ float g_cbT[EDIM * NUM_E];              // codebook transposed [c][k]
__device__ unsigned g_wmaxbits;                    // max ||e||^2 as float bits (nonneg)
__device__ int   g_idx[NROWS];                     // final argmin
__device__ __nv_bfloat16 g_b0[NUM_E * EDIM];       // bf16(codebook) [k][c]
__device__ __nv_bfloat16 g_z0[256 * 8 * 32 * 128]; // bf16(z) tiled [mtile][ch][cr][m]
__device__ __nv_bfloat16 g_dmat[(size_t)NROWS * NUM_E]; // approx distances (64MB)

// ---- smem layout for screen kernel (bytes) ----
#define AS_STRIDE 272                 // 128 m * 2B + 16 pad
#define AS_BUF    (32 * AS_STRIDE)    // 8704
#define BS_OFF    (2 * AS_BUF)        // 17408
#define BS_STRIDE 80
#define BS_BUF    (128 * BS_STRIDE)   // 10240
#define SMEM_TOTAL (BS_OFF + 2 * BS_BUF)  // 37888

__device__ __forceinline__ uint32_t smem_u32(const void* p) {
    uint32_t a;
    asm("{ .reg .u64 t; cvta.to.shared.u64 t, %1; cvt.u32.u64 %0, t; }" : "=r"(a) : "l"(p));
    return a;
}
__device__ __forceinline__ void cpasync16(uint32_t dst, const void* src) {
    asm volatile("cp.async.cg.shared.global [%0], [%1], 16;" :: "r"(dst), "l"(src));
}
__device__ __forceinline__ void ldsm_x4(uint32_t* r, uint32_t addr) {
    asm volatile("ldmatrix.sync.aligned.m8n8.x4.shared.b16 {%0,%1,%2,%3}, [%4];"
                 : "=r"(r[0]), "=r"(r[1]), "=r"(r[2]), "=r"(r[3]) : "r"(addr));
}
__device__ __forceinline__ void ldsm_x4t(uint32_t* r, uint32_t addr) {
    asm volatile("ldmatrix.sync.aligned.m8n8.x4.trans.shared.b16 {%0,%1,%2,%3}, [%4];"
                 : "=r"(r[0]), "=r"(r[1]), "=r"(r[2]), "=r"(r[3]) : "r"(addr));
}
__device__ __forceinline__ void mma16816(float* c, const uint32_t* a, uint32_t b0, uint32_t b1) {
    asm volatile("mma.sync.aligned.m16n8k16.row.col.f32.bf16.bf16.f32 "
                 "{%0,%1,%2,%3}, {%4,%5,%6,%7}, {%8,%9}, {%0,%1,%2,%3};"
                 : "+f"(c[0]), "+f"(c[1]), "+f"(c[2]), "+f"(c[3])
                 : "r"(a[0]), "r"(a[1]), "r"(a[2]), "r"(a[3]), "r"(b0), "r"(b1));
}
__device__ __forceinline__ unsigned ordf(float d) {
    unsigned u = __float_as_uint(d);
    return (u & 0x80000000u) ? ~u : (u | 0x80000000u);
}

// ---------- merged prep: blocks [0,1024) codebook, [1024,3072) z ----------
__global__ __launch_bounds__(256) void prep_kernel(const float* __restrict__ cb,
                                                   const float* __restrict__ z) {
    const int bid = blockIdx.x, t = threadIdx.x;
    if (bid < 1024) {
        int k = bid;
        float v = cb[(size_t)k * EDIM + t];
        g_cbT[(size_t)t * NUM_E + k] = v;
        g_b0[(size_t)k * EDIM + t] = __float2bfloat16(v);
        float sq = v * v;
        #pragma unroll
        for (int o = 16; o; o >>= 1) sq += __shfl_down_sync(0xffffffffu, sq, o);
        __shared__ float ws[8];
        if ((t & 31) == 0) ws[t >> 5] = sq;
        __syncthreads();
        if (t == 0) {
            float s = 0.f;
            #pragma unroll
            for (int i = 0; i < 8; i++) s += ws[i];
            g_cbnorm[k] = s;
            atomicMax(&g_wmaxbits, __float_as_uint(s));
        }
    } else {
        const int zb = bid - 1024;               // zb = mtile*8 + ch
        const int mtile = zb >> 3, ch = zb & 7;
        const int cr = t >> 3, ms = (t & 7) * 16;
        const int m0 = mtile * 128;
        const float* src = z + ((size_t)(m0 >> 10) << 18) + (size_t)(ch * 32 + cr) * 1024 + (m0 & 1023) + ms;
        uint32_t o0[8];
        #pragma unroll
        for (int q = 0; q < 4; q++) {
            float4 f = ((const float4*)src)[q];
            __nv_bfloat162 v0 = __halves2bfloat162(__float2bfloat16(f.x), __float2bfloat16(f.y));
            __nv_bfloat162 v1 = __halves2bfloat162(__float2bfloat16(f.z), __float2bfloat16(f.w));
            o0[q * 2] = *(uint32_t*)&v0; o0[q * 2 + 1] = *(uint32_t*)&v1;
        }
        __nv_bfloat16* dst = g_z0 + ((size_t)zb * 32 + cr) * 128 + ms;
        ((uint4*)dst)[0] = *(uint4*)&o0[0];
        ((uint4*)dst)[1] = *(uint4*)&o0[4];
    }
}

// ---- async tile loaders ----
__device__ __forceinline__ void issue_A(uint32_t dst, int mtile, int ch, int tid) {
    #pragma unroll
    for (int r = 0; r < 2; r++) {
        int e = tid + r * 256;
        int seg = e & 15, cr = e >> 4;
        cpasync16(dst + cr * AS_STRIDE + seg * 16,
                  g_z0 + ((size_t)(mtile * 8 + ch) * 32 + cr) * 128 + seg * 8);
    }
}
__device__ __forceinline__ void issue_B(uint32_t dst, int n0, int c0, int tid) {
    #pragma unroll
    for (int r = 0; r < 2; r++) {
        int e = tid + r * 256;
        int seg = e & 3, bn = e >> 2;
        cpasync16(dst + bn * BS_STRIDE + seg * 16,
                  g_b0 + (size_t)(n0 + bn) * EDIM + c0 + seg * 8);
    }
}

// ---------- screen: bf16 GEMM -> approx distance matrix (bf16) ----------
// grid = 2048 (256 mtiles x 8 ntiles), block = 256
__global__ __launch_bounds__(256, 2) void screen_kernel() {
    extern __shared__ __align__(16) unsigned char smem[];
    const uint32_t sb = smem_u32(smem);
    const int tid = threadIdx.x;
    const int lane = tid & 31;
    const int w = tid >> 5, wm = w & 1, wn = w >> 1;   // 2 m-warps x 4 n-warps
    const int ntile = blockIdx.x & 7, mtile = blockIdx.x >> 3;
    const int m0 = mtile * 128, n0 = ntile * 128;

    float acc[4][4][4];
    #pragma unroll
    for (int i = 0; i < 4; i++)
        #pragma unroll
        for (int j = 0; j < 4; j++)
            #pragma unroll
            for (int e = 0; e < 4; e++) acc[i][j][e] = 0.f;

    issue_A(sb, mtile, 0, tid);
    issue_B(sb + BS_OFF, n0, 0, tid);
    asm volatile("cp.async.commit_group;");

    const int sel = lane >> 3, rr = lane & 7;
    #pragma unroll 1
    for (int ch = 0; ch < 8; ch++) {
        const int buf = ch & 1;
        if (ch < 7) {
            const int nbuf = buf ^ 1;
            issue_A(sb + nbuf * AS_BUF, mtile, ch + 1, tid);
            issue_B(sb + BS_OFF + nbuf * BS_BUF, n0, (ch + 1) * 32, tid);
            asm volatile("cp.async.commit_group;");
            asm volatile("cp.async.wait_group 1;");
        } else {
            asm volatile("cp.async.wait_group 0;");
        }
        __syncthreads();

        const uint32_t asB = sb + buf * AS_BUF;
        const uint32_t bsB = sb + BS_OFF + buf * BS_BUF;
        #pragma unroll
        for (int ks = 0; ks < 2; ks++) {
            const int k0 = ks * 16;
            uint32_t bb[8];
            uint32_t baddr = bsB + (wn * 32 + (sel >> 1) * 8 + rr) * BS_STRIDE + (k0 + (sel & 1) * 8) * 2;
            ldsm_x4(bb, baddr);
            ldsm_x4(bb + 4, baddr + 16 * BS_STRIDE);
            #pragma unroll
            for (int i = 0; i < 4; i++) {
                uint32_t a[4];
                uint32_t aaddr = asB + (k0 + (sel >> 1) * 8 + rr) * AS_STRIDE
                               + (wm * 64 + i * 16 + (sel & 1) * 8) * 2;
                ldsm_x4t(a, aaddr);
                #pragma unroll
                for (int j = 0; j < 4; j++)
                    mma16816(acc[i][j], a, bb[2 * j], bb[2 * j + 1]);
            }
        }
        __syncthreads();
    }

    // epilogue: d~ = ||e||^2 - 2 s0, store bf16
    const int g = lane >> 2, tg = lane & 3;
    float cbn[8];
    #pragma unroll
    for (int j = 0; j < 4; j++) {
        cbn[2 * j]     = __ldg(&g_cbnorm[n0 + wn * 32 + j * 8 + tg * 2]);
        cbn[2 * j + 1] = __ldg(&g_cbnorm[n0 + wn * 32 + j * 8 + tg * 2 + 1]);
    }
    #pragma unroll
    for (int i = 0; i < 4; i++) {
        #pragma unroll
        for (int h = 0; h < 2; h++) {
            int row = m0 + wm * 64 + i * 16 + h * 8 + g;
            #pragma unroll
            for (int j = 0; j < 4; j++) {
                float d0 = cbn[2 * j]     - 2.0f * acc[i][j][h * 2];
                float d1 = cbn[2 * j + 1] - 2.0f * acc[i][j][h * 2 + 1];
                int col = n0 + wn * 32 + j * 8 + tg * 2;
                __nv_bfloat162 v = __halves2bfloat162(__float2bfloat16(d0), __float2bfloat16(d1));
                *(uint32_t*)(g_dmat + (size_t)row * NUM_E + col) = *(uint32_t*)&v;
            }
        }
    }
}

// ---------- pass 2: scan + exact refine (warp per row, 8 rows/block) ----------
// lane-mask candidate discovery (1 ballot), warp-cooperative exact dots
__global__ __launch_bounds__(256) void refine_kernel(const float* __restrict__ z,
                                                     const float* __restrict__ cb) {
    __shared__ float zrow[8][256];
    const int bid = blockIdx.x, tid = threadIdx.x;
    const int w = tid >> 5, lane = tid & 31;
    const int r0 = bid * 8, b = r0 >> 10, hw0 = r0 & 1023;
    for (int e = tid; e < 2048; e += 256) {
        int rr = e & 7, c = e >> 3;
        zrow[rr][c] = z[(size_t)b * 262144 + (size_t)c * 1024 + hw0 + rr];
    }
    __syncthreads();
    const int row = r0 + w;

    float zn2 = 0.f;
    #pragma unroll
    for (int i = 0; i < 8; i++) { float v = zrow[w][lane + 32 * i]; zn2 += v * v; }
    #pragma unroll
    for (int o = 16; o; o >>= 1) zn2 += __shfl_xor_sync(0xffffffffu, zn2, o);

    // vectorized dmat scan: 4 x uint4 (8 bf16 each); dv[iq*8+j] -> col (iq*32+lane)*8+j
    const uint4* d4 = (const uint4*)(g_dmat + (size_t)row * NUM_E) + lane;
    uint4 qv[4];
    #pragma unroll
    for (int i = 0; i < 4; i++) qv[i] = d4[i * 32];
    float dv[32];
    float dmin = 3.4e38f;
    #pragma unroll
    for (int i = 0; i < 4; i++) {
        const uint32_t* pp = (const uint32_t*)&qv[i];
        #pragma unroll
        for (int hj = 0; hj < 4; hj++) {
            __nv_bfloat162 h = *(const __nv_bfloat162*)&pp[hj];
            float lo = __bfloat162float(__low2bfloat16(h));
            float hi = __bfloat162float(__high2bfloat16(h));
            dv[i * 8 + hj * 2]     = lo;
            dv[i * 8 + hj * 2 + 1] = hi;
            dmin = fminf(dmin, fminf(lo, hi));
        }
    }
    #pragma unroll
    for (int o = 16; o; o >>= 1) dmin = fminf(dmin, __shfl_xor_sync(0xffffffffu, dmin, o));

    float wmax = sqrtf(__uint_as_float(g_wmaxbits));      // max ||e||
    float T = dmin + 0.025f * sqrtf(zn2) * wmax + 8.0f;   // >3x proven bound

    // build per-lane candidate mask (no syncs), then ONE ballot
    unsigned cmask = 0;
    #pragma unroll
    for (int i = 0; i < 32; i++)
        if (dv[i] <= T) cmask |= (1u << i);

    unsigned long long best = ~0ull;
    unsigned active = __ballot_sync(0xffffffffu, cmask != 0);
    while (active) {
        int src = __ffs(active) - 1; active &= active - 1;
        unsigned bm = __shfl_sync(0xffffffffu, cmask, src);
        while (bm) {
            int i = __ffs(bm) - 1; bm &= bm - 1;
            int kc = ((i >> 3) * 32 + src) * 8 + (i & 7);
            const float* erow = cb + (size_t)kc * EDIM;
            float s = 0.f;
            #pragma unroll
            for (int jj = 0; jj < 8; jj++)
                s += zrow[w][lane + 32 * jj] * __ldg(&erow[lane + 32 * jj]);
            #pragma unroll
            for (int o = 16; o; o >>= 1) s += __shfl_xor_sync(0xffffffffu, s, o);
            float dist = __ldg(&g_cbnorm[kc]) - 2.0f * s;
            unsigned long long key = ((unsigned long long)ordf(dist) << 32) | (unsigned)kc;
            if (key < best) best = key;   // s warp-uniform -> best warp-uniform
        }
    }
    if (lane == 0) g_idx[row] = (int)(best & 0xFFFFFFFFu);
}

// ---------- outputs: quant gather (blocks < 8192), one-hot scatter (rest) ----------
__global__ __launch_bounds__(256) void finish_kernel(float* __restrict__ oh, float* __restrict__ oq) {
    int bid = blockIdx.x, t = threadIdx.x;
    if (bid < 8192) {
        int i = bid * 256 + t;
        int flat = i * 4;
        int hw = flat & 1023, c = (flat >> 10) & 255, b = flat >> 18;
        int r0 = b * 1024 + hw;
        int4 idx4;
        idx4.x = g_idx[r0]; idx4.y = g_idx[r0 + 1]; idx4.z = g_idx[r0 + 2]; idx4.w = g_idx[r0 + 3];
        const float* rowp = &g_cbT[(size_t)c * NUM_E];
        float4 v;
        v.x = rowp[idx4.x]; v.y = rowp[idx4.y]; v.z = rowp[idx4.z]; v.w = rowp[idx4.w];
        *(float4*)&oq[flat] = v;
    } else {
        int row = (bid - 8192) * 256 + t;
        oh[(size_t)row * NUM_E + g_idx[row]] = 1.0f;
    }
}

extern "C" void kernel_launch(void* const* d_in, const int* in_sizes, int n_in,
                              void* d_out, int out_size) {
    const float* z  = (const float*)d_in[0];
    const float* cb = (const float*)d_in[1];
    float* out_onehot = (float*)d_out;
    float* out_q      = (float*)d_out + (size_t)NROWS * NUM_E;

    cudaFuncSetAttribute(screen_kernel, cudaFuncAttributeMaxDynamicSharedMemorySize, SMEM_TOTAL);

    cudaMemsetAsync(out_onehot, 0, (size_t)NROWS * NUM_E * sizeof(float));
    prep_kernel<<<3072, 256>>>(cb, z);
    screen_kernel<<<2048, 256, SMEM_TOTAL>>>();
    refine_kernel<<<NROWS / 8, 256>>>(z, cb);
    finish_kernel<<<8192 + NROWS / 256, 256>>>(out_onehot, out_q);
}

// round 13
// speedup vs baseline: 2.0031x; 1.0142x over previous
#include <cuda_runtime.h>
#include <cuda_bf16.h>
#include <cstdint>

#define NUM_E 1024
#define EDIM  256
#define NROWS 32768

// ---- device scratch ----
__device__ float g_cbnorm[NUM_E];                  // ||e_k||^2
__device__ unsigned g_wmaxbits;                    // max ||e||^2 as float bits (nonneg)
__device__ __nv_bfloat16 g_b0[NUM_E * EDIM];       // bf16(codebook) [k][c]
__device__ __nv_bfloat16 g_z0[256 * 8 * 32 * 128]; // bf16(z) tiled [mtile][ch][cr][m]
__device__ __nv_bfloat16 g_dmat[(size_t)NROWS * NUM_E]; // approx distances (64MB)

// ---- smem layout for screen kernel (bytes) ----
#define AS_STRIDE 272                 // 128 m * 2B + 16 pad
#define AS_BUF    (32 * AS_STRIDE)    // 8704
#define BS_OFF    (2 * AS_BUF)        // 17408
#define BS_STRIDE 80
#define BS_BUF    (128 * BS_STRIDE)   // 10240
#define SMEM_TOTAL (BS_OFF + 2 * BS_BUF)  // 37888

__device__ __forceinline__ uint32_t smem_u32(const void* p) {
    uint32_t a;
    asm("{ .reg .u64 t; cvta.to.shared.u64 t, %1; cvt.u32.u64 %0, t; }" : "=r"(a) : "l"(p));
    return a;
}
__device__ __forceinline__ void cpasync16(uint32_t dst, const void* src) {
    asm volatile("cp.async.cg.shared.global [%0], [%1], 16;" :: "r"(dst), "l"(src));
}
__device__ __forceinline__ void ldsm_x4(uint32_t* r, uint32_t addr) {
    asm volatile("ldmatrix.sync.aligned.m8n8.x4.shared.b16 {%0,%1,%2,%3}, [%4];"
                 : "=r"(r[0]), "=r"(r[1]), "=r"(r[2]), "=r"(r[3]) : "r"(addr));
}
__device__ __forceinline__ void ldsm_x4t(uint32_t* r, uint32_t addr) {
    asm volatile("ldmatrix.sync.aligned.m8n8.x4.trans.shared.b16 {%0,%1,%2,%3}, [%4];"
                 : "=r"(r[0]), "=r"(r[1]), "=r"(r[2]), "=r"(r[3]) : "r"(addr));
}
__device__ __forceinline__ void mma16816(float* c, const uint32_t* a, uint32_t b0, uint32_t b1) {
    asm volatile("mma.sync.aligned.m16n8k16.row.col.f32.bf16.bf16.f32 "
                 "{%0,%1,%2,%3}, {%4,%5,%6,%7}, {%8,%9}, {%0,%1,%2,%3};"
                 : "+f"(c[0]), "+f"(c[1]), "+f"(c[2]), "+f"(c[3])
                 : "r"(a[0]), "r"(a[1]), "r"(a[2]), "r"(a[3]), "r"(b0), "r"(b1));
}
__device__ __forceinline__ unsigned ordf(float d) {
    unsigned u = __float_as_uint(d);
    return (u & 0x80000000u) ? ~u : (u | 0x80000000u);
}

// ---------- merged prep: blocks [0,1024) codebook, [1024,3072) z ----------
__global__ __launch_bounds__(256) void prep_kernel(const float* __restrict__ cb,
                                                   const float* __restrict__ z) {
    const int bid = blockIdx.x, t = threadIdx.x;
    if (bid < 1024) {
        int k = bid;
        float v = cb[(size_t)k * EDIM + t];
        g_b0[(size_t)k * EDIM + t] = __float2bfloat16(v);
        float sq = v * v;
        #pragma unroll
        for (int o = 16; o; o >>= 1) sq += __shfl_down_sync(0xffffffffu, sq, o);
        __shared__ float ws[8];
        if ((t & 31) == 0) ws[t >> 5] = sq;
        __syncthreads();
        if (t == 0) {
            float s = 0.f;
            #pragma unroll
            for (int i = 0; i < 8; i++) s += ws[i];
            g_cbnorm[k] = s;
            atomicMax(&g_wmaxbits, __float_as_uint(s));
        }
    } else {
        const int zb = bid - 1024;               // zb = mtile*8 + ch
        const int mtile = zb >> 3, ch = zb & 7;
        const int cr = t >> 3, ms = (t & 7) * 16;
        const int m0 = mtile * 128;
        const float* src = z + ((size_t)(m0 >> 10) << 18) + (size_t)(ch * 32 + cr) * 1024 + (m0 & 1023) + ms;
        uint32_t o0[8];
        #pragma unroll
        for (int q = 0; q < 4; q++) {
            float4 f = ((const float4*)src)[q];
            __nv_bfloat162 v0 = __halves2bfloat162(__float2bfloat16(f.x), __float2bfloat16(f.y));
            __nv_bfloat162 v1 = __halves2bfloat162(__float2bfloat16(f.z), __float2bfloat16(f.w));
            o0[q * 2] = *(uint32_t*)&v0; o0[q * 2 + 1] = *(uint32_t*)&v1;
        }
        __nv_bfloat16* dst = g_z0 + ((size_t)zb * 32 + cr) * 128 + ms;
        ((uint4*)dst)[0] = *(uint4*)&o0[0];
        ((uint4*)dst)[1] = *(uint4*)&o0[4];
    }
}

// ---- async tile loaders ----
__device__ __forceinline__ void issue_A(uint32_t dst, int mtile, int ch, int tid) {
    #pragma unroll
    for (int r = 0; r < 2; r++) {
        int e = tid + r * 256;
        int seg = e & 15, cr = e >> 4;
        cpasync16(dst + cr * AS_STRIDE + seg * 16,
                  g_z0 + ((size_t)(mtile * 8 + ch) * 32 + cr) * 128 + seg * 8);
    }
}
__device__ __forceinline__ void issue_B(uint32_t dst, int n0, int c0, int tid) {
    #pragma unroll
    for (int r = 0; r < 2; r++) {
        int e = tid + r * 256;
        int seg = e & 3, bn = e >> 2;
        cpasync16(dst + bn * BS_STRIDE + seg * 16,
                  g_b0 + (size_t)(n0 + bn) * EDIM + c0 + seg * 8);
    }
}

// ---------- screen: bf16 GEMM -> approx distance matrix (bf16) ----------
// grid = 2048 (256 mtiles x 8 ntiles), block = 256
__global__ __launch_bounds__(256, 2) void screen_kernel() {
    extern __shared__ __align__(16) unsigned char smem[];
    const uint32_t sb = smem_u32(smem);
    const int tid = threadIdx.x;
    const int lane = tid & 31;
    const int w = tid >> 5, wm = w & 1, wn = w >> 1;   // 2 m-warps x 4 n-warps
    const int ntile = blockIdx.x & 7, mtile = blockIdx.x >> 3;
    const int m0 = mtile * 128, n0 = ntile * 128;

    float acc[4][4][4];
    #pragma unroll
    for (int i = 0; i < 4; i++)
        #pragma unroll
        for (int j = 0; j < 4; j++)
            #pragma unroll
            for (int e = 0; e < 4; e++) acc[i][j][e] = 0.f;

    issue_A(sb, mtile, 0, tid);
    issue_B(sb + BS_OFF, n0, 0, tid);
    asm volatile("cp.async.commit_group;");

    const int sel = lane >> 3, rr = lane & 7;
    #pragma unroll 1
    for (int ch = 0; ch < 8; ch++) {
        const int buf = ch & 1;
        if (ch < 7) {
            const int nbuf = buf ^ 1;
            issue_A(sb + nbuf * AS_BUF, mtile, ch + 1, tid);
            issue_B(sb + BS_OFF + nbuf * BS_BUF, n0, (ch + 1) * 32, tid);
            asm volatile("cp.async.commit_group;");
            asm volatile("cp.async.wait_group 1;");
        } else {
            asm volatile("cp.async.wait_group 0;");
        }
        __syncthreads();

        const uint32_t asB = sb + buf * AS_BUF;
        const uint32_t bsB = sb + BS_OFF + buf * BS_BUF;
        #pragma unroll
        for (int ks = 0; ks < 2; ks++) {
            const int k0 = ks * 16;
            uint32_t bb[8];
            uint32_t baddr = bsB + (wn * 32 + (sel >> 1) * 8 + rr) * BS_STRIDE + (k0 + (sel & 1) * 8) * 2;
            ldsm_x4(bb, baddr);
            ldsm_x4(bb + 4, baddr + 16 * BS_STRIDE);
            #pragma unroll
            for (int i = 0; i < 4; i++) {
                uint32_t a[4];
                uint32_t aaddr = asB + (k0 + (sel >> 1) * 8 + rr) * AS_STRIDE
                               + (wm * 64 + i * 16 + (sel & 1) * 8) * 2;
                ldsm_x4t(a, aaddr);
                #pragma unroll
                for (int j = 0; j < 4; j++)
                    mma16816(acc[i][j], a, bb[2 * j], bb[2 * j + 1]);
            }
        }
        __syncthreads();
    }

    // epilogue: d~ = ||e||^2 - 2 s0, store bf16
    const int g = lane >> 2, tg = lane & 3;
    float cbn[8];
    #pragma unroll
    for (int j = 0; j < 4; j++) {
        cbn[2 * j]     = __ldg(&g_cbnorm[n0 + wn * 32 + j * 8 + tg * 2]);
        cbn[2 * j + 1] = __ldg(&g_cbnorm[n0 + wn * 32 + j * 8 + tg * 2 + 1]);
    }
    #pragma unroll
    for (int i = 0; i < 4; i++) {
        #pragma unroll
        for (int h = 0; h < 2; h++) {
            int row = m0 + wm * 64 + i * 16 + h * 8 + g;
            #pragma unroll
            for (int j = 0; j < 4; j++) {
                float d0 = cbn[2 * j]     - 2.0f * acc[i][j][h * 2];
                float d1 = cbn[2 * j + 1] - 2.0f * acc[i][j][h * 2 + 1];
                int col = n0 + wn * 32 + j * 8 + tg * 2;
                __nv_bfloat162 v = __halves2bfloat162(__float2bfloat16(d0), __float2bfloat16(d1));
                *(uint32_t*)(g_dmat + (size_t)row * NUM_E + col) = *(uint32_t*)&v;
            }
        }
    }
}

// ---------- pass 2: scan + exact refine + fused outputs (warp per row, 8 rows/block) ----------
__global__ __launch_bounds__(256) void refine_kernel(const float* __restrict__ z,
                                                     const float* __restrict__ cb,
                                                     float* __restrict__ oh,
                                                     float* __restrict__ oq) {
    __shared__ float zrow[8][256];
    __shared__ int sidx[8];
    const int bid = blockIdx.x, tid = threadIdx.x;
    const int w = tid >> 5, lane = tid & 31;
    const int r0 = bid * 8, b = r0 >> 10, hw0 = r0 & 1023;
    for (int e = tid; e < 2048; e += 256) {
        int rr = e & 7, c = e >> 3;
        zrow[rr][c] = z[(size_t)b * 262144 + (size_t)c * 1024 + hw0 + rr];
    }
    __syncthreads();
    const int row = r0 + w;

    float zn2 = 0.f;
    #pragma unroll
    for (int i = 0; i < 8; i++) { float v = zrow[w][lane + 32 * i]; zn2 += v * v; }
    #pragma unroll
    for (int o = 16; o; o >>= 1) zn2 += __shfl_xor_sync(0xffffffffu, zn2, o);

    // vectorized dmat scan: 4 x uint4 (8 bf16 each); dv[iq*8+j] -> col (iq*32+lane)*8+j
    const uint4* d4 = (const uint4*)(g_dmat + (size_t)row * NUM_E) + lane;
    uint4 qv[4];
    #pragma unroll
    for (int i = 0; i < 4; i++) qv[i] = d4[i * 32];
    float dv[32];
    float dmin = 3.4e38f;
    #pragma unroll
    for (int i = 0; i < 4; i++) {
        const uint32_t* pp = (const uint32_t*)&qv[i];
        #pragma unroll
        for (int hj = 0; hj < 4; hj++) {
            __nv_bfloat162 h = *(const __nv_bfloat162*)&pp[hj];
            float lo = __bfloat162float(__low2bfloat16(h));
            float hi = __bfloat162float(__high2bfloat16(h));
            dv[i * 8 + hj * 2]     = lo;
            dv[i * 8 + hj * 2 + 1] = hi;
            dmin = fminf(dmin, fminf(lo, hi));
        }
    }
    #pragma unroll
    for (int o = 16; o; o >>= 1) dmin = fminf(dmin, __shfl_xor_sync(0xffffffffu, dmin, o));

    float wmax = sqrtf(__uint_as_float(g_wmaxbits));      // max ||e||
    float T = dmin + 0.025f * sqrtf(zn2) * wmax + 8.0f;   // >3x proven bound

    // build per-lane candidate mask (no syncs), then ONE ballot
    unsigned cmask = 0;
    #pragma unroll
    for (int i = 0; i < 32; i++)
        if (dv[i] <= T) cmask |= (1u << i);

    unsigned long long best = ~0ull;
    unsigned active = __ballot_sync(0xffffffffu, cmask != 0);
    while (active) {
        int src = __ffs(active) - 1; active &= active - 1;
        unsigned bm = __shfl_sync(0xffffffffu, cmask, src);
        while (bm) {
            int i = __ffs(bm) - 1; bm &= bm - 1;
            int kc = ((i >> 3) * 32 + src) * 8 + (i & 7);
            const float* erow = cb + (size_t)kc * EDIM;
            float s = 0.f;
            #pragma unroll
            for (int jj = 0; jj < 8; jj++)
                s += zrow[w][lane + 32 * jj] * __ldg(&erow[lane + 32 * jj]);
            #pragma unroll
            for (int o = 16; o; o >>= 1) s += __shfl_xor_sync(0xffffffffu, s, o);
            float dist = __ldg(&g_cbnorm[kc]) - 2.0f * s;
            unsigned long long key = ((unsigned long long)ordf(dist) << 32) | (unsigned)kc;
            if (key < best) best = key;   // s warp-uniform -> best warp-uniform
        }
    }
    if (lane == 0) sidx[w] = (int)(best & 0xFFFFFFFFu);
    __syncthreads();

    // ---- fused outputs ----
    int idx[8];
    #pragma unroll
    for (int r = 0; r < 8; r++) idx[r] = sidx[r];

    // one-hot: 8 rows x 1024, float4 per thread per row
    #pragma unroll
    for (int r = 0; r < 8; r++) {
        int id = idx[r];
        float4 v = {0.f, 0.f, 0.f, 0.f};
        if ((id >> 2) == tid) {
            if ((id & 3) == 0) v.x = 1.f;
            else if ((id & 3) == 1) v.y = 1.f;
            else if ((id & 3) == 2) v.z = 1.f;
            else v.w = 1.f;
        }
        *(float4*)&oh[(size_t)(r0 + r) * NUM_E + tid * 4] = v;
    }

    // quant: thread t = channel c; vals[r] = cb[idx[r]*256 + c]; contiguous 8-float store
    float vals[8];
    #pragma unroll
    for (int r = 0; r < 8; r++)
        vals[r] = __ldg(&cb[(size_t)idx[r] * EDIM + tid]);
    float* qbase = oq + (size_t)b * 262144 + (size_t)tid * 1024 + hw0;
    *(float4*)qbase       = *(float4*)&vals[0];
    *(float4*)(qbase + 4) = *(float4*)&vals[4];
}

extern "C" void kernel_launch(void* const* d_in, const int* in_sizes, int n_in,
                              void* d_out, int out_size) {
    const float* z  = (const float*)d_in[0];
    const float* cb = (const float*)d_in[1];
    float* out_onehot = (float*)d_out;
    float* out_q      = (float*)d_out + (size_t)NROWS * NUM_E;

    cudaFuncSetAttribute(screen_kernel, cudaFuncAttributeMaxDynamicSharedMemorySize, SMEM_TOTAL);

    prep_kernel<<<3072, 256>>>(cb, z);
    screen_kernel<<<2048, 256, SMEM_TOTAL>>>();
    refine_kernel<<<NROWS / 8, 256>>>(z, cb, out_onehot, out_q);
}